// round 8
// baseline (speedup 1.0000x reference)
#include <cuda_runtime.h>
#include <math.h>
#include <stdint.h>

#define K_CTX 64
#define D_DIM 128
#define C_CAND 256
#define DS 200
#define EPS 1e-8f
#define GRID_B 128   // 2 candidates per block

// Scratch + sync (device globals; no allocation allowed)
__device__ __align__(16) float g_A[K_CTX * D_DIM];
__device__ __align__(16) float g_AM[K_CTX * D_DIM];
__device__ int g_count = 0;   // AM rows produced
__device__ int g_done  = 0;   // blocks finished (reset)

// sB row stride 140 floats (560B, 16B aligned): LDS.128 conflict-free
#define SB_STRIDE 140
#define SB_ROW_BYTES (SB_STRIDE * 4)   // 560
#define SB_FLOATS (K_CTX * SB_STRIDE)  // 8960
#define SMEM_FLOATS (8192 + 2*SB_FLOATS + 2*64 + 64 + 64 + 64 + 128 + 128 + 1024 + 8 + 8)

__device__ __forceinline__ uint32_t smem_u32(const void* p) {
    return (uint32_t)__cvta_generic_to_shared(p);
}
__device__ __forceinline__ void mbar_init(uint32_t mbar, uint32_t cnt) {
    asm volatile("mbarrier.init.shared.b64 [%0], %1;" :: "r"(mbar), "r"(cnt) : "memory");
}
__device__ __forceinline__ void mbar_expect_tx(uint32_t mbar, uint32_t bytes) {
    asm volatile("mbarrier.arrive.expect_tx.shared.b64 _, [%0], %1;"
                 :: "r"(mbar), "r"(bytes) : "memory");
}
__device__ __forceinline__ void mbar_wait(uint32_t mbar, uint32_t parity) {
    uint32_t done;
    asm volatile(
        "{\n\t.reg .pred p;\n\t"
        "mbarrier.try_wait.parity.acquire.cta.shared::cta.b64 p, [%1], %2;\n\t"
        "selp.b32 %0, 1, 0, p;\n\t}"
        : "=r"(done) : "r"(mbar), "r"(parity) : "memory");
    if (!done) {
        asm volatile(
            "{\n\t.reg .pred P1;\n\t"
            "WAIT_LOOP_%=:\n\t"
            "mbarrier.try_wait.parity.acquire.cta.shared::cta.b64 P1, [%0], %1, 0x989680;\n\t"
            "@P1 bra.uni WAIT_DONE_%=;\n\t"
            "bra.uni WAIT_LOOP_%=;\n\t"
            "WAIT_DONE_%=:\n\t}"
            :: "r"(mbar), "r"(parity) : "memory");
    }
}
__device__ __forceinline__ void bulk_g2s(uint32_t dst_smem, const void* src_gmem,
                                         uint32_t bytes, uint32_t mbar) {
    asm volatile(
        "cp.async.bulk.shared::cluster.global.mbarrier::complete_tx::bytes "
        "[%0], [%1], %2, [%3];"
        :: "r"(dst_smem), "l"(src_gmem), "r"(bytes), "r"(mbar) : "memory");
}
__device__ __forceinline__ float tanh_fast(float x) {
    float y;
    asm("tanh.approx.f32 %0, %1;" : "=f"(y) : "f"(x));
    return y;
}

// ---------------------------------------------------------------------------
// grid = 128, block = 512. Block b handles candidates 2b, 2b+1.
// Blocks 0..63 additionally produce one AM row.
// ---------------------------------------------------------------------------
__global__ __launch_bounds__(512, 1)
void cand_kernel(const float* __restrict__ table,
                 const float* __restrict__ str_t1,
                 const float* __restrict__ str_t2s,
                 const float* __restrict__ att_mat,
                 const float* __restrict__ W,     // W_bi[0]: [128,128]
                 const float* __restrict__ b_bi,
                 const int* __restrict__ t1_ctx,
                 const int* __restrict__ t2_ctx,
                 float* __restrict__ out) {
    extern __shared__ __align__(16) float sm[];
    float* sAM     = sm;                         // 64*128 (producer scratch too)
    float* sB0     = sAM + K_CTX * D_DIM;        // 64*140
    float* sB1     = sB0 + SB_FLOATS;            // 64*140
    float* colsum0 = sB1 + SB_FLOATS;            // 64
    float* colsum1 = colsum0 + K_CTX;            // 64
    float* rowsum  = colsum1 + K_CTX;            // 64
    float* rows_w  = rowsum + K_CTX;             // 64
    float* cols_w  = rows_w + K_CTX;             // 64
    float* newA    = cols_w + K_CTX;             // 128 (producer arow)
    float* newB    = newA + D_DIM;               // 128
    float* scratch = newB + D_DIM;               // 1024 (tail partials)
    float* scal    = scratch + 1024;             // 8: [0..3]=c0, [4..7]=c1
    uint64_t* mbars = (uint64_t*)(scal + 8);     // [0]=g0 [1]=g1 [2]=sAM

    const int b    = blockIdx.x;
    const int c0   = 2 * b;
    const int c1   = 2 * b + 1;
    const int tid  = threadIdx.x;
    const int wid  = tid >> 5;
    const int lane = tid & 31;
    const uint32_t mbar_g0 = smem_u32(&mbars[0]);
    const uint32_t mbar_g1 = smem_u32(&mbars[1]);
    const uint32_t mbar_a  = smem_u32(&mbars[2]);

    // --- phase 0: init mbars + zero accumulators ---
    if (tid == 0) {
        mbar_init(mbar_g0, 1);
        mbar_init(mbar_g1, 1);
        mbar_init(mbar_a, 1);
        mbar_expect_tx(mbar_g0, K_CTX * D_DIM * 4);
        mbar_expect_tx(mbar_g1, K_CTX * D_DIM * 4);
        mbar_expect_tx(mbar_a,  K_CTX * D_DIM * 4);
    }
    if (tid < K_CTX) { colsum0[tid] = 0.f; colsum1[tid] = 0.f; }
    if (tid < 8) scal[tid] = 0.f;
    __syncthreads();   // mbar init visible before complete_tx can land

    // --- phase 1: issue both candidates' B gathers (64 rows x 512B each) ---
    const int* ctx0 = t2_ctx + c0 * K_CTX;
    const int* ctx1 = t2_ctx + c1 * K_CTX;
    if (tid < K_CTX) {
        bulk_g2s(smem_u32(sB0) + tid * SB_ROW_BYTES,
                 table + (long long)ctx0[tid] * D_DIM, D_DIM * 4, mbar_g0);
    } else if (tid < 2 * K_CTX) {
        int m = tid - K_CTX;
        bulk_g2s(smem_u32(sB1) + m * SB_ROW_BYTES,
                 table + (long long)ctx1[m] * D_DIM, D_DIM * 4, mbar_g1);
    }

    // --- phase 2: producer — blocks 0..63 compute AM row b ---
    if (b < K_CTX) {
        if (tid < D_DIM) {
            float a = table[(long long)t1_ctx[b] * D_DIM + tid];
            newA[tid] = a;
            g_A[b * D_DIM + tid] = a;
        }
        __syncthreads();
        {
            const int d = tid & 127;
            const int q = tid >> 7;
            const float* att = att_mat + (q * 32) * D_DIM + d;
            const float* ar  = newA + q * 32;
            float acc = 0.f;
#pragma unroll
            for (int e = 0; e < 32; e++)
                acc = fmaf(ar[e], att[e * D_DIM], acc);
            sAM[tid] = acc;
        }
        __syncthreads();
        if (tid < D_DIM) {
            g_AM[b * D_DIM + tid] = sAM[tid] + sAM[D_DIM + tid]
                                  + sAM[2 * D_DIM + tid] + sAM[3 * D_DIM + tid];
            __threadfence();
        }
        __syncthreads();
        if (tid == 0) atomicAdd(&g_count, 1);
    }

    // --- phase 3: string cosine partials for both candidates ---
    {
        int half = tid >> 8;                  // 0 -> c0, 1 -> c1
        int j = tid & 255;
        int cc = half ? c1 : c0;
        float* sc = scal + 4 * half;
        float pd = 0.f, p1 = 0.f, p2 = 0.f;
        if (j < DS) {
            float x1 = str_t1[j];
            float x2 = str_t2s[cc * DS + j];
            pd = x1 * x2; p1 = x1 * x1; p2 = x2 * x2;
        }
#pragma unroll
        for (int off = 16; off; off >>= 1) {
            pd += __shfl_down_sync(0xffffffffu, pd, off);
            p1 += __shfl_down_sync(0xffffffffu, p1, off);
            p2 += __shfl_down_sync(0xffffffffu, p2, off);
        }
        if (lane == 0 && (wid & 7) < 7) {
            atomicAdd(&sc[0], pd);
            atomicAdd(&sc[1], p1);
            atomicAdd(&sc[2], p2);
        }
    }

    // --- phase 4: wait producers, one 32KB bulk copy of AM ---
    if (tid == 0) {
        while (((volatile int*)&g_count)[0] < K_CTX) {}
        __threadfence();
        asm volatile("fence.proxy.async;" ::: "memory");
        bulk_g2s(smem_u32(sAM), g_AM, K_CTX * D_DIM * 4, mbar_a);
    }
    mbar_wait(mbar_a, 0);

    // ======================= per-candidate pipeline =======================
#pragma unroll 1
    for (int half = 0; half < 2; half++) {
        float* sB     = half ? sB1 : sB0;
        float* colsum = half ? colsum1 : colsum0;
        float* sc     = scal + 4 * half;
        const int cc  = half ? c1 : c0;
        const int* ctx = half ? ctx1 : ctx0;

        mbar_wait(half ? mbar_g1 : mbar_g0, 0);
        __syncthreads();

        // --- sim = tanh(AM @ B^T): warp w -> k 4w..4w+3; lane -> m l, l+32 ---
        {
            const float4* am0 = (const float4*)(sAM + (wid * 4 + 0) * D_DIM);
            const float4* am1 = (const float4*)(sAM + (wid * 4 + 1) * D_DIM);
            const float4* am2 = (const float4*)(sAM + (wid * 4 + 2) * D_DIM);
            const float4* am3 = (const float4*)(sAM + (wid * 4 + 3) * D_DIM);
            const float4* b0p = (const float4*)(sB + lane * SB_STRIDE);
            const float4* b1p = (const float4*)(sB + (lane + 32) * SB_STRIDE);

            float acc00 = 0, acc01 = 0;
            float acc10 = 0, acc11 = 0;
            float acc20 = 0, acc21 = 0;
            float acc30 = 0, acc31 = 0;

#pragma unroll 4
            for (int jv = 0; jv < D_DIM / 4; jv++) {
                float4 a0 = am0[jv];
                float4 a1 = am1[jv];
                float4 a2 = am2[jv];
                float4 a3 = am3[jv];
                float4 v0 = b0p[jv];
                float4 v1 = b1p[jv];

                acc00 = fmaf(a0.x, v0.x, acc00); acc00 = fmaf(a0.y, v0.y, acc00);
                acc00 = fmaf(a0.z, v0.z, acc00); acc00 = fmaf(a0.w, v0.w, acc00);
                acc01 = fmaf(a0.x, v1.x, acc01); acc01 = fmaf(a0.y, v1.y, acc01);
                acc01 = fmaf(a0.z, v1.z, acc01); acc01 = fmaf(a0.w, v1.w, acc01);

                acc10 = fmaf(a1.x, v0.x, acc10); acc10 = fmaf(a1.y, v0.y, acc10);
                acc10 = fmaf(a1.z, v0.z, acc10); acc10 = fmaf(a1.w, v0.w, acc10);
                acc11 = fmaf(a1.x, v1.x, acc11); acc11 = fmaf(a1.y, v1.y, acc11);
                acc11 = fmaf(a1.z, v1.z, acc11); acc11 = fmaf(a1.w, v1.w, acc11);

                acc20 = fmaf(a2.x, v0.x, acc20); acc20 = fmaf(a2.y, v0.y, acc20);
                acc20 = fmaf(a2.z, v0.z, acc20); acc20 = fmaf(a2.w, v0.w, acc20);
                acc21 = fmaf(a2.x, v1.x, acc21); acc21 = fmaf(a2.y, v1.y, acc21);
                acc21 = fmaf(a2.z, v1.z, acc21); acc21 = fmaf(a2.w, v1.w, acc21);

                acc30 = fmaf(a3.x, v0.x, acc30); acc30 = fmaf(a3.y, v0.y, acc30);
                acc30 = fmaf(a3.z, v0.z, acc30); acc30 = fmaf(a3.w, v0.w, acc30);
                acc31 = fmaf(a3.x, v1.x, acc31); acc31 = fmaf(a3.y, v1.y, acc31);
                acc31 = fmaf(a3.z, v1.z, acc31); acc31 = fmaf(a3.w, v1.w, acc31);
            }

            float s00 = tanh_fast(acc00), s01 = tanh_fast(acc01);
            float s10 = tanh_fast(acc10), s11 = tanh_fast(acc11);
            float s20 = tanh_fast(acc20), s21 = tanh_fast(acc21);
            float s30 = tanh_fast(acc30), s31 = tanh_fast(acc31);

            float r0 = s00 + s01;
            float r1 = s10 + s11;
            float r2 = s20 + s21;
            float r3 = s30 + s31;
#pragma unroll
            for (int off = 16; off; off >>= 1) {
                r0 += __shfl_xor_sync(0xffffffffu, r0, off);
                r1 += __shfl_xor_sync(0xffffffffu, r1, off);
                r2 += __shfl_xor_sync(0xffffffffu, r2, off);
                r3 += __shfl_xor_sync(0xffffffffu, r3, off);
            }
            if (lane == 0) {
                rowsum[wid * 4 + 0] = r0;
                rowsum[wid * 4 + 1] = r1;
                rowsum[wid * 4 + 2] = r2;
                rowsum[wid * 4 + 3] = r3;
            }
            atomicAdd(&colsum[lane],      s00 + s10 + s20 + s30);
            atomicAdd(&colsum[lane + 32], s01 + s11 + s21 + s31);
        }
        __syncthreads();

        // --- softmax over 64: warp 0 -> rows, warp 1 -> cols ---
        if (tid < 64) {
            const float* src = (tid < 32) ? rowsum : colsum;
            float* dst       = (tid < 32) ? rows_w : cols_w;
            int l = tid & 31;
            float v0 = src[l]      * (1.f / 64.f);
            float v1 = src[l + 32] * (1.f / 64.f);
            float mx = fmaxf(v0, v1);
#pragma unroll
            for (int off = 16; off; off >>= 1)
                mx = fmaxf(mx, __shfl_xor_sync(0xffffffffu, mx, off));
            float e0 = __expf(v0 - mx);
            float e1 = __expf(v1 - mx);
            float s = e0 + e1;
#pragma unroll
            for (int off = 16; off; off >>= 1)
                s += __shfl_xor_sync(0xffffffffu, s, off);
            float inv = 1.f / s;
            dst[l]      = e0 * inv;
            dst[l + 32] = e1 * inv;
        }
        __syncthreads();

        // --- new_A / new_B with all 512 threads (4-way k partials) ---
        {
            const int d = tid & 127;
            const int q = tid >> 7;
            float na = 0.f, nb = 0.f;
            const float* gA = g_A + (q * 16) * D_DIM + d;
            const float* sb = sB + (q * 16) * SB_STRIDE + d;
#pragma unroll
            for (int k = 0; k < 16; k++) {
                na = fmaf(rows_w[q * 16 + k], __ldg(gA + k * D_DIM), na);
                nb = fmaf(cols_w[q * 16 + k], sb[k * SB_STRIDE], nb);
            }
            scratch[tid]       = na;
            scratch[512 + tid] = nb;
        }
        __syncthreads();
        if (tid < D_DIM) {
            newA[tid] = scratch[tid] + scratch[128 + tid]
                      + scratch[256 + tid] + scratch[384 + tid];
            newB[tid] = scratch[512 + tid] + scratch[640 + tid]
                      + scratch[768 + tid] + scratch[896 + tid];
        }
        __syncthreads();

        // --- con = newA @ W @ newB + b (4-way d partials) ---
        {
            const int e = tid & 127;
            const int q = tid >> 7;
            const float* wp = W + (q * 32) * D_DIM + e;
            const float* ap = newA + q * 32;
            float s1 = 0.f;
#pragma unroll
            for (int d = 0; d < 32; d++)
                s1 = fmaf(ap[d], wp[d * D_DIM], s1);
            scratch[tid] = s1;
        }
        __syncthreads();
        if (tid < D_DIM) {
            float s1 = scratch[tid] + scratch[128 + tid]
                     + scratch[256 + tid] + scratch[384 + tid];
            float pc = s1 * newB[tid];
#pragma unroll
            for (int off = 16; off; off >>= 1)
                pc += __shfl_down_sync(0xffffffffu, pc, off);
            if (lane == 0) atomicAdd(&sc[3], pc);
        }
        __syncthreads();

        if (tid == 0) {
            float n1 = fmaxf(sqrtf(sc[1]), EPS);
            float n2 = fmaxf(sqrtf(sc[2]), EPS);
            float str_score = sc[0] / (n1 * n2);
            float con_score = sc[3] + b_bi[0];
            out[cc] = 0.5f * str_score + 0.5f * con_score;
        }
        __syncthreads();   // scratch/rowsum reuse safety for next half
    }

    // --- counter reset for graph replay ---
    if (tid == 0) {
        __threadfence();
        int d = atomicAdd(&g_done, 1);
        if (d == GRID_B - 1) {
            g_done  = 0;
            g_count = 0;
        }
    }
}

// ---------------------------------------------------------------------------
extern "C" void kernel_launch(void* const* d_in, const int* in_sizes, int n_in,
                              void* d_out, int out_size) {
    const float* table   = (const float*)d_in[0];
    const float* str_t1  = (const float*)d_in[1];
    const float* str_t2s = (const float*)d_in[2];
    const float* att_mat = (const float*)d_in[3];
    const float* W_bi    = (const float*)d_in[4];
    const float* b_bi    = (const float*)d_in[5];
    const int*   t1_ctx  = (const int*)d_in[6];
    const int*   t2_ctx  = (const int*)d_in[7];
    float* out = (float*)d_out;

    cudaFuncSetAttribute(cand_kernel,
                         cudaFuncAttributeMaxDynamicSharedMemorySize,
                         SMEM_FLOATS * sizeof(float));

    cand_kernel<<<GRID_B, 512, SMEM_FLOATS * sizeof(float)>>>(
        table, str_t1, str_t2s, att_mat, W_bi, b_bi, t1_ctx, t2_ctx, out);
}

// round 9
// speedup vs baseline: 1.0694x; 1.0694x over previous
#include <cuda_runtime.h>
#include <math.h>
#include <stdint.h>

#define K_CTX 64
#define D_DIM 128
#define C_CAND 256
#define DS 200
#define EPS 1e-8f

// Scratch + sync (device globals; no allocation allowed)
__device__ __align__(16) float g_A[K_CTX * D_DIM];
__device__ __align__(16) float g_AM[K_CTX * D_DIM];
__device__ int g_count = 0;   // AM rows produced
__device__ int g_done  = 0;   // blocks finished (reset)

// sB row stride 140 floats (560B, 16B aligned): LDS.128 conflict-free
#define SB_STRIDE 140
#define SB_ROW_BYTES (SB_STRIDE * 4)   // 560
#define SMEM_FLOATS (8192 + K_CTX * SB_STRIDE + 4 * 64 + 2 * 128 + 4 + 4)

__device__ __forceinline__ uint32_t smem_u32(const void* p) {
    return (uint32_t)__cvta_generic_to_shared(p);
}
__device__ __forceinline__ void mbar_init(uint32_t mbar, uint32_t cnt) {
    asm volatile("mbarrier.init.shared.b64 [%0], %1;" :: "r"(mbar), "r"(cnt) : "memory");
}
__device__ __forceinline__ void mbar_expect_tx(uint32_t mbar, uint32_t bytes) {
    asm volatile("mbarrier.arrive.expect_tx.shared.b64 _, [%0], %1;"
                 :: "r"(mbar), "r"(bytes) : "memory");
}
__device__ __forceinline__ void mbar_wait(uint32_t mbar, uint32_t parity) {
    uint32_t done;
    asm volatile(
        "{\n\t.reg .pred p;\n\t"
        "mbarrier.try_wait.parity.acquire.cta.shared::cta.b64 p, [%1], %2;\n\t"
        "selp.b32 %0, 1, 0, p;\n\t}"
        : "=r"(done) : "r"(mbar), "r"(parity) : "memory");
    if (!done) {
        asm volatile(
            "{\n\t.reg .pred P1;\n\t"
            "WAIT_LOOP_%=:\n\t"
            "mbarrier.try_wait.parity.acquire.cta.shared::cta.b64 P1, [%0], %1, 0x989680;\n\t"
            "@P1 bra.uni WAIT_DONE_%=;\n\t"
            "bra.uni WAIT_LOOP_%=;\n\t"
            "WAIT_DONE_%=:\n\t}"
            :: "r"(mbar), "r"(parity) : "memory");
    }
}
__device__ __forceinline__ void bulk_g2s(uint32_t dst_smem, const void* src_gmem,
                                         uint32_t bytes, uint32_t mbar) {
    asm volatile(
        "cp.async.bulk.shared::cluster.global.mbarrier::complete_tx::bytes "
        "[%0], [%1], %2, [%3];"
        :: "r"(dst_smem), "l"(src_gmem), "r"(bytes), "r"(mbar) : "memory");
}
__device__ __forceinline__ float tanh_fast(float x) {
    float y;
    asm("tanh.approx.f32 %0, %1;" : "=f"(y) : "f"(x));
    return y;
}
// Packed fp32x2 FMA (Blackwell): d = a*b + c elementwise on two packed floats.
__device__ __forceinline__ unsigned long long ffma2(unsigned long long a,
                                                    unsigned long long b,
                                                    unsigned long long c) {
    unsigned long long d;
    asm("fma.rn.f32x2 %0, %1, %2, %3;" : "=l"(d) : "l"(a), "l"(b), "l"(c));
    return d;
}
__device__ __forceinline__ float f32x2_hsum(unsigned long long v) {
    float lo = __uint_as_float((unsigned)(v & 0xffffffffull));
    float hi = __uint_as_float((unsigned)(v >> 32));
    return lo + hi;
}

// ---------------------------------------------------------------------------
// Single fused kernel. grid = 256 (one block per candidate), block = 512.
// Blocks 0..63 additionally produce one AM row.
// ---------------------------------------------------------------------------
__global__ __launch_bounds__(512, 3)
void cand_kernel(const float* __restrict__ table,
                 const float* __restrict__ str_t1,
                 const float* __restrict__ str_t2s,
                 const float* __restrict__ att_mat,
                 const float* __restrict__ W,     // W_bi[0]: [128,128]
                 const float* __restrict__ b_bi,
                 const int* __restrict__ t1_ctx,
                 const int* __restrict__ t2_ctx,
                 float* __restrict__ out) {
    extern __shared__ __align__(16) float sm[];
    float* sAM    = sm;                        // 64*128 (producer/tail scratch)
    float* sB     = sAM + K_CTX * D_DIM;       // 64*140
    float* rowsum = sB + K_CTX * SB_STRIDE;    // 64
    float* colsum = rowsum + K_CTX;            // 64
    float* rows_w = colsum + K_CTX;            // 64
    float* cols_w = rows_w + K_CTX;            // 64
    float* newA   = cols_w + K_CTX;            // 128 (producer arow)
    float* newB   = newA + D_DIM;              // 128
    float* scal   = newB + D_DIM;              // 4
    uint64_t* mbars = (uint64_t*)(scal + 4);   // [0]=gather, [1]=sAM stage

    const int c    = blockIdx.x;
    const int tid  = threadIdx.x;
    const int wid  = tid >> 5;                 // 0..15
    const int lane = tid & 31;
    const uint32_t mbar_g = smem_u32(&mbars[0]);
    const uint32_t mbar_a = smem_u32(&mbars[1]);

    // --- phase 0: init mbarriers + zero accumulators ---
    if (tid == 0) {
        mbar_init(mbar_g, 1);
        mbar_init(mbar_a, 1);
        mbar_expect_tx(mbar_g, K_CTX * D_DIM * 4);
        mbar_expect_tx(mbar_a, K_CTX * D_DIM * 4);
    }
    if (tid < K_CTX) colsum[tid] = 0.f;
    if (tid < 4) scal[tid] = 0.f;
    __syncthreads();

    // --- phase 1: kick off B-row gather via 64 bulk copies (512B each) ---
    const int* ctx = t2_ctx + c * K_CTX;
    if (tid < K_CTX) {
        bulk_g2s(smem_u32(sB) + tid * SB_ROW_BYTES,
                 table + (long long)ctx[tid] * D_DIM,
                 D_DIM * 4, mbar_g);
    }

    // --- phase 2: producer — blocks 0..63 compute AM row c (512 threads) ---
    if (c < K_CTX) {
        if (tid < D_DIM) {
            float a = table[(long long)t1_ctx[c] * D_DIM + tid];
            newA[tid] = a;
            g_A[c * D_DIM + tid] = a;
        }
        __syncthreads();
        {
            const int d = tid & 127;
            const int q = tid >> 7;
            const float* att = att_mat + (q * 32) * D_DIM + d;
            const float* ar  = newA + q * 32;
            float acc = 0.f;
#pragma unroll
            for (int e = 0; e < 32; e++)
                acc = fmaf(ar[e], att[e * D_DIM], acc);
            sAM[tid] = acc;
        }
        __syncthreads();
        if (tid < D_DIM) {
            g_AM[c * D_DIM + tid] = sAM[tid] + sAM[D_DIM + tid]
                                  + sAM[2 * D_DIM + tid] + sAM[3 * D_DIM + tid];
            __threadfence();
        }
        __syncthreads();
        if (tid == 0) atomicAdd(&g_count, 1);
    } else {
        __syncthreads();
        __syncthreads();
        __syncthreads();
    }

    // --- phase 3: string cosine partials (hides latency) ---
    {
        float pd = 0.f, p1 = 0.f, p2 = 0.f;
        if (tid < DS) {
            float x1 = str_t1[tid];
            float x2 = str_t2s[c * DS + tid];
            pd = x1 * x2; p1 = x1 * x1; p2 = x2 * x2;
        }
#pragma unroll
        for (int off = 16; off; off >>= 1) {
            pd += __shfl_down_sync(0xffffffffu, pd, off);
            p1 += __shfl_down_sync(0xffffffffu, p1, off);
            p2 += __shfl_down_sync(0xffffffffu, p2, off);
        }
        if (lane == 0 && wid < 7) {
            atomicAdd(&scal[0], pd);
            atomicAdd(&scal[1], p1);
            atomicAdd(&scal[2], p2);
        }
    }

    // --- phase 4: wait producers, then one 32KB bulk copy of AM ---
    if (tid == 0) {
        while (((volatile int*)&g_count)[0] < K_CTX) {}
        __threadfence();
        asm volatile("fence.proxy.async;" ::: "memory");
        bulk_g2s(smem_u32(sAM), g_AM, K_CTX * D_DIM * 4, mbar_a);
    }

    // --- phase 5: wait both bulk transfers, then block barrier ---
    mbar_wait(mbar_g, 0);
    mbar_wait(mbar_a, 0);
    __syncthreads();

    // --- phase 6: sim = tanh(AM @ B^T) with packed f32x2 FMAs ---
    // warp w -> k rows 4w..4w+3; lane -> m cols l, l+32.
    {
        const ulonglong2* am0 = (const ulonglong2*)(sAM + (wid * 4 + 0) * D_DIM);
        const ulonglong2* am1 = (const ulonglong2*)(sAM + (wid * 4 + 1) * D_DIM);
        const ulonglong2* am2 = (const ulonglong2*)(sAM + (wid * 4 + 2) * D_DIM);
        const ulonglong2* am3 = (const ulonglong2*)(sAM + (wid * 4 + 3) * D_DIM);
        const ulonglong2* b0p = (const ulonglong2*)(sB + lane * SB_STRIDE);
        const ulonglong2* b1p = (const ulonglong2*)(sB + (lane + 32) * SB_STRIDE);

        unsigned long long acc00 = 0, acc01 = 0;
        unsigned long long acc10 = 0, acc11 = 0;
        unsigned long long acc20 = 0, acc21 = 0;
        unsigned long long acc30 = 0, acc31 = 0;

#pragma unroll 4
        for (int jv = 0; jv < D_DIM / 4; jv++) {   // 4 floats = 2 packed pairs
            ulonglong2 a0 = am0[jv];
            ulonglong2 a1 = am1[jv];
            ulonglong2 a2 = am2[jv];
            ulonglong2 a3 = am3[jv];
            ulonglong2 b0 = b0p[jv];
            ulonglong2 b1 = b1p[jv];

            acc00 = ffma2(a0.x, b0.x, acc00); acc00 = ffma2(a0.y, b0.y, acc00);
            acc01 = ffma2(a0.x, b1.x, acc01); acc01 = ffma2(a0.y, b1.y, acc01);
            acc10 = ffma2(a1.x, b0.x, acc10); acc10 = ffma2(a1.y, b0.y, acc10);
            acc11 = ffma2(a1.x, b1.x, acc11); acc11 = ffma2(a1.y, b1.y, acc11);
            acc20 = ffma2(a2.x, b0.x, acc20); acc20 = ffma2(a2.y, b0.y, acc20);
            acc21 = ffma2(a2.x, b1.x, acc21); acc21 = ffma2(a2.y, b1.y, acc21);
            acc30 = ffma2(a3.x, b0.x, acc30); acc30 = ffma2(a3.y, b0.y, acc30);
            acc31 = ffma2(a3.x, b1.x, acc31); acc31 = ffma2(a3.y, b1.y, acc31);
        }

        float s00 = tanh_fast(f32x2_hsum(acc00)), s01 = tanh_fast(f32x2_hsum(acc01));
        float s10 = tanh_fast(f32x2_hsum(acc10)), s11 = tanh_fast(f32x2_hsum(acc11));
        float s20 = tanh_fast(f32x2_hsum(acc20)), s21 = tanh_fast(f32x2_hsum(acc21));
        float s30 = tanh_fast(f32x2_hsum(acc30)), s31 = tanh_fast(f32x2_hsum(acc31));

        float r0 = s00 + s01;
        float r1 = s10 + s11;
        float r2 = s20 + s21;
        float r3 = s30 + s31;
#pragma unroll
        for (int off = 16; off; off >>= 1) {
            r0 += __shfl_xor_sync(0xffffffffu, r0, off);
            r1 += __shfl_xor_sync(0xffffffffu, r1, off);
            r2 += __shfl_xor_sync(0xffffffffu, r2, off);
            r3 += __shfl_xor_sync(0xffffffffu, r3, off);
        }
        if (lane == 0) {
            rowsum[wid * 4 + 0] = r0;
            rowsum[wid * 4 + 1] = r1;
            rowsum[wid * 4 + 2] = r2;
            rowsum[wid * 4 + 3] = r3;
        }
        atomicAdd(&colsum[lane],      s00 + s10 + s20 + s30);
        atomicAdd(&colsum[lane + 32], s01 + s11 + s21 + s31);
    }
    __syncthreads();

    // --- phase 7: softmax over 64: warp 0 -> rows, warp 1 -> cols ---
    if (tid < 64) {
        const float* src = (tid < 32) ? rowsum : colsum;
        float* dst       = (tid < 32) ? rows_w : cols_w;
        int l = tid & 31;
        float v0 = src[l]      * (1.f / 64.f);
        float v1 = src[l + 32] * (1.f / 64.f);
        float mx = fmaxf(v0, v1);
#pragma unroll
        for (int off = 16; off; off >>= 1)
            mx = fmaxf(mx, __shfl_xor_sync(0xffffffffu, mx, off));
        float e0 = __expf(v0 - mx);
        float e1 = __expf(v1 - mx);
        float s = e0 + e1;
#pragma unroll
        for (int off = 16; off; off >>= 1)
            s += __shfl_xor_sync(0xffffffffu, s, off);
        float inv = 1.f / s;
        dst[l]      = e0 * inv;
        dst[l + 32] = e1 * inv;
    }
    __syncthreads();

    // --- phase 8: new_A / new_B with all 512 threads (4-way k partials) ---
    {
        const int d = tid & 127;
        const int q = tid >> 7;            // 0..3 -> k range [16q, 16q+16)
        float na = 0.f, nb = 0.f;
        const float* gA = g_A + (q * 16) * D_DIM + d;
        const float* sb = sB + (q * 16) * SB_STRIDE + d;
#pragma unroll
        for (int k = 0; k < 16; k++) {
            na = fmaf(rows_w[q * 16 + k], __ldg(gA + k * D_DIM), na);
            nb = fmaf(cols_w[q * 16 + k], sb[k * SB_STRIDE], nb);
        }
        sAM[tid]       = na;               // sAM free after sim: partial scratch
        sAM[512 + tid] = nb;
    }
    __syncthreads();
    if (tid < D_DIM) {
        newA[tid] = sAM[tid] + sAM[128 + tid] + sAM[256 + tid] + sAM[384 + tid];
        newB[tid] = sAM[512 + tid] + sAM[640 + tid] + sAM[768 + tid] + sAM[896 + tid];
    }
    __syncthreads();

    // --- phase 9: con = newA @ W @ newB + b (4-way d partials) ---
    {
        const int e = tid & 127;
        const int q = tid >> 7;            // d range [32q, 32q+32)
        const float* wp = W + (q * 32) * D_DIM + e;
        const float* ap = newA + q * 32;
        float s1 = 0.f;
#pragma unroll
        for (int d = 0; d < 32; d++)
            s1 = fmaf(ap[d], wp[d * D_DIM], s1);
        sAM[tid] = s1;
    }
    __syncthreads();
    if (tid < D_DIM) {
        float s1 = sAM[tid] + sAM[128 + tid] + sAM[256 + tid] + sAM[384 + tid];
        float pc = s1 * newB[tid];
#pragma unroll
        for (int off = 16; off; off >>= 1)
            pc += __shfl_down_sync(0xffffffffu, pc, off);
        if (lane == 0) atomicAdd(&scal[3], pc);
    }
    __syncthreads();

    if (tid == 0) {
        float n1 = fmaxf(sqrtf(scal[1]), EPS);
        float n2 = fmaxf(sqrtf(scal[2]), EPS);
        float str_score = scal[0] / (n1 * n2);
        float con_score = scal[3] + b_bi[0];
        out[c] = 0.5f * str_score + 0.5f * con_score;

        int d = atomicAdd(&g_done, 1);
        if (d == C_CAND - 1) {
            g_done  = 0;
            g_count = 0;
        }
    }
}

// ---------------------------------------------------------------------------
extern "C" void kernel_launch(void* const* d_in, const int* in_sizes, int n_in,
                              void* d_out, int out_size) {
    const float* table   = (const float*)d_in[0];
    const float* str_t1  = (const float*)d_in[1];
    const float* str_t2s = (const float*)d_in[2];
    const float* att_mat = (const float*)d_in[3];
    const float* W_bi    = (const float*)d_in[4];
    const float* b_bi    = (const float*)d_in[5];
    const int*   t1_ctx  = (const int*)d_in[6];
    const int*   t2_ctx  = (const int*)d_in[7];
    float* out = (float*)d_out;

    cudaFuncSetAttribute(cand_kernel,
                         cudaFuncAttributeMaxDynamicSharedMemorySize,
                         SMEM_FLOATS * sizeof(float));

    cand_kernel<<<C_CAND, 512, SMEM_FLOATS * sizeof(float)>>>(
        table, str_t1, str_t2s, att_mat, W_bi, b_bi, t1_ctx, t2_ctx, out);
}